// round 4
// baseline (speedup 1.0000x reference)
#include <cuda_runtime.h>
#include <math.h>

#define N     1024
#define NN    (N*N)
#define NB    32
#define NSTEP 32
#define BATCH 16

// ---------------- device scratch (no allocations allowed) ----------------
__device__ float g_lu[(size_t)BATCH * NN];   // 64 MB destructible LU workspace
__device__ float g_comb[(size_t)3 * NN];     // combined right-hand matrices C0,C1,C2
__device__ float g_logdet[BATCH];
__device__ int   g_perm[2][BATCH * N];       // double-buffered row permutations

struct Hdr {
    int   active;
    int   idx[8];
    float weff[10];
    float beff;
};
__device__ Hdr g_hdr;

// ---------------- stage A: copy x -> LU workspace, init perm + logdets ----------------
__global__ void copy_kernel(const float* __restrict__ x) {
    size_t i = (size_t)blockIdx.x * blockDim.x + threadIdx.x;
    const float4* src = (const float4*)x;
    float4* dst = (float4*)g_lu;
    if (i < (size_t)BATCH * NN / 4) dst[i] = src[i];
    if (i < BATCH * N) g_perm[0][i] = (int)(i % N);   // identity per matrix
    if (i < BATCH) g_logdet[i] = 0.0f;
}

// ---------------- panel: narrow update (step k-1) + pivoted factor of cols [c1,c1+32) ----
// One CTA per matrix, 512 threads, 2 register-resident rows per thread.
// Reads perm[k&1], writes perm[(k+1)&1]. No physical trailing swaps (lazy perm).
__global__ void __launch_bounds__(512) lu_panel(int k) {
    int m = blockIdx.x;
    float* A = g_lu + (size_t)m * NN;
    const int* pin  = g_perm[k & 1] + m * N;
    int*       pout = g_perm[(k + 1) & 1] + m * N;
    int c1 = k * NB;
    int Rp = N - c1;
    int tid = threadIdx.x;

    __shared__ int   sh_perm[N];
    __shared__ float Dp[NB][NB + 1];
    __shared__ float U12[NB][NB + 1];
    __shared__ float s_piv[NB];
    __shared__ float s_rowj[NB];
    __shared__ float rv[16];
    __shared__ int   ri[16];
    __shared__ int   s_prel;

    // perm: head copied out directly, tail staged in shared
    for (int r = tid; r < Rp; r += 512) sh_perm[r] = pin[c1 + r];
    for (int r = tid; r < c1; r += 512) pout[r] = pin[r];
    __syncthreads();

    // ---- phase 1 (k>0): load D(k-1), solve U12n for this panel's 32 columns ----
    if (k > 0) {
        int kbp = c1 - NB;
        for (int i = tid; i < NB * NB; i += 512) {
            int r = i / NB, c = i % NB;
            Dp[r][c] = A[(size_t)pin[kbp + r] * N + kbp + c];
        }
        __syncthreads();
        if (tid < NB) {
            int c = tid;
            float v[NB];
            #pragma unroll
            for (int i = 0; i < NB; i++) v[i] = A[(size_t)pin[kbp + i] * N + c1 + c];
            #pragma unroll 1
            for (int j = 0; j < NB; j++) {
                float vj = v[j];
                #pragma unroll
                for (int i2 = 0; i2 < NB; i2++)
                    if (i2 > j) v[i2] -= Dp[i2][j] * vj;
            }
            #pragma unroll
            for (int i = 0; i < NB; i++) U12[i][c] = v[i];
        }
        __syncthreads();
    }

    // ---- phase 2: load my rows (registers) + apply step-(k-1) narrow update ----
    float ra[NB], rb[NB];
    int relA = tid, relB = tid + 512;
    bool hasA = relA < Rp, hasB = relB < Rp;
    int physA = hasA ? sh_perm[relA] : 0;
    int physB = hasB ? sh_perm[relB] : 0;

    {
        const float4* pA = (const float4*)(A + (size_t)physA * N + c1);
        const float4* pB = (const float4*)(A + (size_t)physB * N + c1);
        #pragma unroll
        for (int q = 0; q < 8; q++) {
            float4 v = hasA ? pA[q] : make_float4(0.f, 0.f, 0.f, 0.f);
            ra[4*q+0] = v.x; ra[4*q+1] = v.y; ra[4*q+2] = v.z; ra[4*q+3] = v.w;
            float4 w = hasB ? pB[q] : make_float4(0.f, 0.f, 0.f, 0.f);
            rb[4*q+0] = w.x; rb[4*q+1] = w.y; rb[4*q+2] = w.z; rb[4*q+3] = w.w;
        }
    }
    if (k > 0) {
        int kbp = c1 - NB;
        if (hasA) {
            const float* lrow = A + (size_t)physA * N + kbp;
            #pragma unroll
            for (int j = 0; j < NB; j++) {
                float lj = lrow[j];
                #pragma unroll
                for (int c = 0; c < NB; c++) ra[c] -= lj * U12[j][c];
            }
        }
        if (hasB) {
            const float* lrow = A + (size_t)physB * N + kbp;
            #pragma unroll
            for (int j = 0; j < NB; j++) {
                float lj = lrow[j];
                #pragma unroll
                for (int c = 0; c < NB; c++) rb[c] -= lj * U12[j][c];
            }
        }
    }
    __syncthreads();

    // ---- phase 3: pivoted factorization of the 32-wide panel (rows in registers) ----
    float sld = 0.0f;
    #pragma unroll 1
    for (int j = 0; j < NB; j++) {
        // candidate extraction (static-index predicated selects)
        float va = -1.0f; int ia = 0x7fffffff;
        if (hasA && relA >= j) {
            float x = 0.0f;
            #pragma unroll
            for (int jj = 0; jj < NB; jj++) if (jj == j) x = ra[jj];
            va = fabsf(x); ia = relA;
        }
        if (hasB && relB >= j) {
            float x = 0.0f;
            #pragma unroll
            for (int jj = 0; jj < NB; jj++) if (jj == j) x = rb[jj];
            float vx = fabsf(x);
            if (vx > va || (vx == va && relB < ia)) { va = vx; ia = relB; }
        }
        float best = va; int bi = ia;
        #pragma unroll
        for (int o = 16; o > 0; o >>= 1) {
            float ov = __shfl_down_sync(0xffffffffu, best, o);
            int   oi = __shfl_down_sync(0xffffffffu, bi, o);
            if (ov > best || (ov == best && oi < bi)) { best = ov; bi = oi; }
        }
        if ((tid & 31) == 0) { rv[tid >> 5] = best; ri[tid >> 5] = bi; }
        __syncthreads();
        if (tid < 32) {
            float b2 = (tid < 16) ? rv[tid] : -2.0f;
            int   i2 = (tid < 16) ? ri[tid] : 0x7fffffff;
            #pragma unroll
            for (int o = 8; o > 0; o >>= 1) {
                float ov = __shfl_down_sync(0xffffffffu, b2, o);
                int   oi = __shfl_down_sync(0xffffffffu, i2, o);
                if (ov > b2 || (ov == b2 && oi < i2)) { b2 = ov; i2 = oi; }
            }
            if (tid == 0) {
                s_prel = i2;
                sld += logf(fmaxf(b2, 1e-45f));
                if (i2 != j) { int t2 = sh_perm[j]; sh_perm[j] = sh_perm[i2]; sh_perm[i2] = t2; }
            }
        }
        __syncthreads();
        int p = s_prel;
        // stage pivot row (and row j if swapping)
        if (hasA && relA == p) {
            #pragma unroll
            for (int jj = 0; jj < NB; jj++) s_piv[jj] = ra[jj];
        }
        if (hasB && relB == p) {
            #pragma unroll
            for (int jj = 0; jj < NB; jj++) s_piv[jj] = rb[jj];
        }
        if (p != j) {
            if (hasA && relA == j) {
                #pragma unroll
                for (int jj = 0; jj < NB; jj++) s_rowj[jj] = ra[jj];
            }
            if (hasB && relB == j) {
                #pragma unroll
                for (int jj = 0; jj < NB; jj++) s_rowj[jj] = rb[jj];
            }
        }
        __syncthreads();
        // exchange register rows
        if (p != j) {
            if (hasA && relA == j) {
                #pragma unroll
                for (int jj = 0; jj < NB; jj++) ra[jj] = s_piv[jj];
            }
            if (hasB && relB == j) {
                #pragma unroll
                for (int jj = 0; jj < NB; jj++) rb[jj] = s_piv[jj];
            }
            if (hasA && relA == p) {
                #pragma unroll
                for (int jj = 0; jj < NB; jj++) ra[jj] = s_rowj[jj];
            }
            if (hasB && relB == p) {
                #pragma unroll
                for (int jj = 0; jj < NB; jj++) rb[jj] = s_rowj[jj];
            }
        }
        float inv = 1.0f / s_piv[j];
        // eliminate rows rel > j
        if (hasA && relA > j) {
            float x = 0.0f;
            #pragma unroll
            for (int jj = 0; jj < NB; jj++) if (jj == j) x = ra[jj];
            float lv = x * inv;
            #pragma unroll
            for (int jj = 0; jj < NB; jj++) {
                if (jj == j) ra[jj] = lv;
                else if (jj > j) ra[jj] -= lv * s_piv[jj];
            }
        }
        if (hasB && relB > j) {
            float x = 0.0f;
            #pragma unroll
            for (int jj = 0; jj < NB; jj++) if (jj == j) x = rb[jj];
            float lv = x * inv;
            #pragma unroll
            for (int jj = 0; jj < NB; jj++) {
                if (jj == j) rb[jj] = lv;
                else if (jj > j) rb[jj] -= lv * s_piv[jj];
            }
        }
    }
    __syncthreads();

    // ---- phase 4: write perm tail + factored panel (through NEW perm) ----
    for (int r = tid; r < Rp; r += 512) pout[c1 + r] = sh_perm[r];
    if (hasA) {
        float4* pw = (float4*)(A + (size_t)sh_perm[relA] * N + c1);
        #pragma unroll
        for (int q = 0; q < 8; q++)
            pw[q] = make_float4(ra[4*q+0], ra[4*q+1], ra[4*q+2], ra[4*q+3]);
    }
    if (hasB) {
        float4* pw = (float4*)(A + (size_t)sh_perm[relB] * N + c1);
        #pragma unroll
        for (int q = 0; q < 8; q++)
            pw[q] = make_float4(rb[4*q+0], rb[4*q+1], rb[4*q+2], rb[4*q+3]);
    }
    if (tid == 0) g_logdet[m] += sld;
}

// ---------------- wide update: cols [kb+2*NB, N), rows [kb+NB, N), via perm ----------------
__global__ void __launch_bounds__(256) lu_wide(int k) {
    int kb   = k * NB;
    int off  = kb + NB;          // row start
    int coff = kb + 2 * NB;      // col start (narrow cols handled by next panel)
    int Wr = N - off;
    int Wc = N - coff;
    int m  = blockIdx.z;
    float* A = g_lu + (size_t)m * NN;
    const int* perm = g_perm[(k + 1) & 1] + m * N;
    int r0 = blockIdx.y * 128, c0v = blockIdx.x * 64;
    int tid = threadIdx.x;

    __shared__ float D[NB][NB + 1];
    __shared__ float sL[128][NB + 1];
    __shared__ float sU[NB][68];
    __shared__ int   pr[128];
    __shared__ int   pd[NB];

    if (tid < 128) pr[tid] = (r0 + tid < Wr) ? perm[off + r0 + tid] : perm[off];
    else if (tid < 160) pd[tid - 128] = perm[kb + (tid - 128)];
    __syncthreads();

    for (int i = tid; i < NB * NB; i += 256) {
        int r = i / NB, c = i % NB;
        D[r][c] = A[(size_t)pd[r] * N + kb + c];
    }
    for (int i = tid; i < 128 * NB; i += 256) {
        int r = i / NB, j = i % NB;
        sL[r][j] = (r0 + r < Wr) ? A[(size_t)pr[r] * N + kb + j] : 0.0f;
    }
    for (int i = tid; i < NB * 64; i += 256) {
        int r = i / 64, c = i % 64;
        int col = c0v + c;
        sU[r][c] = (col < Wc) ? A[(size_t)pd[r] * N + coff + col] : 0.0f;
    }
    __syncthreads();

    // local TRSM: threads 0..63 each solve one U12 column (L11 unit-lower)
    if (tid < 64) {
        float v[NB];
        #pragma unroll
        for (int i = 0; i < NB; i++) v[i] = sU[i][tid];
        #pragma unroll 1
        for (int j = 0; j < NB; j++) {
            float vj = v[j];
            #pragma unroll
            for (int i = 0; i < NB; i++)
                if (i > j) v[i] -= D[i][j] * vj;
        }
        #pragma unroll
        for (int i = 0; i < NB; i++) sU[i][tid] = v[i];
    }
    __syncthreads();

    // trailing update: 128x64 tile, 8x4 per thread
    int tx = tid & 15, ty = tid >> 4;
    float acc[8][4] = {};
    #pragma unroll
    for (int j = 0; j < NB; j++) {
        float4 bv = *(const float4*)&sU[j][tx * 4];
        float b[4] = {bv.x, bv.y, bv.z, bv.w};
        float a[8];
        #pragma unroll
        for (int i = 0; i < 8; i++) a[i] = sL[ty * 8 + i][j];
        #pragma unroll
        for (int i = 0; i < 8; i++)
            #pragma unroll
            for (int l = 0; l < 4; l++) acc[i][l] += a[i] * b[l];
    }
    #pragma unroll
    for (int i = 0; i < 8; i++) {
        int row = ty * 8 + i;
        if (r0 + row >= Wr) continue;
        float* orow = A + (size_t)pr[row] * N + coff;
        #pragma unroll
        for (int l = 0; l < 4; l++) {
            int col = c0v + tx * 4 + l;
            if (col < Wc) orow[col] -= acc[i][l];
        }
    }
}

// ---------------- stage C: scores, top-k, fused weights, bool output ----------------
__global__ void head_kernel(const unsigned char* __restrict__ flags,
                            const float* __restrict__ w1, const float* __restrict__ b1,
                            const float* __restrict__ w2, const float* __restrict__ b2,
                            float* __restrict__ out, int out_size) {
    if (blockIdx.x != 0 || threadIdx.x != 0) return;

    int f[16];
    bool any_off4 = false;
    for (int i = 0; i < 16; i++)
        if ((i & 3) && flags[i]) any_off4 = true;
    if (any_off4) {
        for (int i = 0; i < 16; i++) f[i] = flags[i] ? 1 : 0;
    } else {
        const int* fi = (const int*)flags;
        for (int i = 0; i < 16; i++) f[i] = fi[i] ? 1 : 0;
    }

    int sum = 0;
    for (int i = 0; i < 16; i++) sum += f[i];
    int active = (sum >= 4) ? 1 : 0;

    float neg_inf = __int_as_float(0xff800000);
    float sc[16];
    for (int i = 0; i < 16; i++) sc[i] = f[i] ? g_logdet[i] : neg_inf;

    int used[16] = {};
    for (int t = 0; t < 8; t++) {
        int best = -1;
        float bv = neg_inf;
        for (int i = 0; i < 16; i++) {
            if (used[i]) continue;
            if (best < 0 || sc[i] > bv) { best = i; bv = sc[i]; }
        }
        used[best] = 1;
        g_hdr.idx[t] = best;
    }

    for (int c = 0; c < 10; c++) {
        float a = 0.0f;
        for (int h = 0; h < 32; h++) a += w2[h] * w1[h * 10 + c];
        g_hdr.weff[c] = a;
    }
    float be = b2[0];
    for (int h = 0; h < 32; h++) be += w2[h] * b1[h];
    g_hdr.beff = be;
    g_hdr.active = active;

    for (int i = NN; i < out_size; i++) out[i] = active ? 1.0f : 0.0f;
}

// ---------------- stage D1: combined right matrices ----------------
__global__ void combine_kernel(const float* __restrict__ x) {
    int i = blockIdx.x * blockDim.x + threadIdx.x;
    if (i >= NN / 4) return;
    const float4* T1 = (const float4*)(x + (size_t)g_hdr.idx[1] * NN);
    const float4* T2 = (const float4*)(x + (size_t)g_hdr.idx[2] * NN);
    const float4* T3 = (const float4*)(x + (size_t)g_hdr.idx[3] * NN);
    float w0 = g_hdr.weff[0], w1 = g_hdr.weff[1], w2 = g_hdr.weff[2];
    float w3 = g_hdr.weff[3], w4 = g_hdr.weff[4], w5 = g_hdr.weff[5];
    float4 a = T1[i], b = T2[i], c = T3[i];
    float4 r0, r1, r2;
    r0.x = w0*a.x + w1*b.x + w2*c.x;  r0.y = w0*a.y + w1*b.y + w2*c.y;
    r0.z = w0*a.z + w1*b.z + w2*c.z;  r0.w = w0*a.w + w1*b.w + w2*c.w;
    r1.x = w3*b.x + w4*c.x;  r1.y = w3*b.y + w4*c.y;
    r1.z = w3*b.z + w4*c.z;  r1.w = w3*b.w + w4*c.w;
    r2.x = w5*c.x;  r2.y = w5*c.y;  r2.z = w5*c.z;  r2.w = w5*c.w;
    ((float4*)g_comb)[i]            = r0;
    ((float4*)(g_comb + NN))[i]     = r1;
    ((float4*)(g_comb + 2*NN))[i]   = r2;
}

// ---------------- stage D2: fused 3-GEMM + preserve channels + bias ----------------
#define SA(p,r,j) sA[((p) * 128 + (r)) * 33 + (j)]
#define SB(p,j,c) sB[((p) * NB + (j)) * 68 + (c)]
__global__ void __launch_bounds__(256) final_kernel(const float* __restrict__ x,
                                                    float* __restrict__ out, int out_size) {
    extern __shared__ float sm[];
    float* sA = sm;                         // 3 * 128 * 33
    float* sB = sm + 3 * 128 * 33;          // 3 * NB * 68

    int r0 = blockIdx.y * 128, c0 = blockIdx.x * 64;
    int tid = threadIdx.x, tx = tid & 15, ty = tid >> 4;

    if (!g_hdr.active) {
        #pragma unroll
        for (int i = 0; i < 8; i++) {
            int row = r0 + ty * 8 + i;
            #pragma unroll
            for (int l = 0; l < 4; l++) {
                int p = row * N + c0 + tx * 4 + l;
                if (p < out_size) out[p] = 0.0f;
            }
        }
        return;
    }

    const float* L[3] = { x + (size_t)g_hdr.idx[0] * NN,
                          x + (size_t)g_hdr.idx[1] * NN,
                          x + (size_t)g_hdr.idx[2] * NN };
    const float* C[3] = { g_comb, g_comb + NN, g_comb + 2 * NN };

    float acc[8][4] = {};
    for (int kc = 0; kc < N; kc += NB) {
        #pragma unroll
        for (int p = 0; p < 3; p++) {
            for (int i = tid; i < 128 * NB; i += 256) {
                int r = i / NB, j = i % NB;
                SA(p, r, j) = L[p][(size_t)(r0 + r) * N + kc + j];
            }
            for (int i = tid; i < NB * 64; i += 256) {
                int j = i / 64, c = i % 64;
                SB(p, j, c) = C[p][(size_t)(kc + j) * N + c0 + c];
            }
        }
        __syncthreads();
        #pragma unroll 4
        for (int jj = 0; jj < NB; jj++) {
            #pragma unroll
            for (int p = 0; p < 3; p++) {
                float4 bv = *(const float4*)&SB(p, jj, tx * 4);
                float b[4] = {bv.x, bv.y, bv.z, bv.w};
                float a[8];
                #pragma unroll
                for (int i = 0; i < 8; i++) a[i] = SA(p, ty * 8 + i, jj);
                #pragma unroll
                for (int i = 0; i < 8; i++)
                    #pragma unroll
                    for (int l = 0; l < 4; l++) acc[i][l] += a[i] * b[l];
            }
        }
        __syncthreads();
    }

    const float* P0 = x + (size_t)g_hdr.idx[4] * NN;
    const float* P1 = x + (size_t)g_hdr.idx[5] * NN;
    const float* P2 = x + (size_t)g_hdr.idx[6] * NN;
    const float* P3 = x + (size_t)g_hdr.idx[7] * NN;
    float w6 = g_hdr.weff[6], w7 = g_hdr.weff[7], w8 = g_hdr.weff[8], w9 = g_hdr.weff[9];
    float be = g_hdr.beff;

    #pragma unroll
    for (int i = 0; i < 8; i++) {
        int row = r0 + ty * 8 + i;
        #pragma unroll
        for (int l = 0; l < 4; l++) {
            int col = c0 + tx * 4 + l;
            int p = row * N + col;
            float v = acc[i][l] + w6 * P0[p] + w7 * P1[p] + w8 * P2[p] + w9 * P3[p] + be;
            if (p < out_size) out[p] = v;
        }
    }
}

// ---------------- host launcher: fork-join DAG (panels on side stream) ----------------
extern "C" void kernel_launch(void* const* d_in, const int* in_sizes, int n_in,
                              void* d_out, int out_size) {
    const float*         x     = (const float*)d_in[0];
    const unsigned char* flags = (const unsigned char*)d_in[1];
    const float*         w1    = (const float*)d_in[2];
    const float*         b1    = (const float*)d_in[3];
    const float*         w2    = (const float*)d_in[4];
    const float*         b2    = (const float*)d_in[5];
    float*               out   = (float*)d_out;

    static cudaStream_t sT;
    static cudaEvent_t  evC, evF[NSTEP], evW[NSTEP];
    static int fin_smem = (3 * 128 * 33 + 3 * NB * 68) * (int)sizeof(float);
    static int inited = 0;
    if (!inited) {                      // first call is the uncaptured correctness run
        cudaStreamCreateWithFlags(&sT, cudaStreamNonBlocking);
        cudaEventCreateWithFlags(&evC, cudaEventDisableTiming);
        for (int i = 0; i < NSTEP; i++) {
            cudaEventCreateWithFlags(&evF[i], cudaEventDisableTiming);
            cudaEventCreateWithFlags(&evW[i], cudaEventDisableTiming);
        }
        cudaFuncSetAttribute(final_kernel, cudaFuncAttributeMaxDynamicSharedMemorySize, fin_smem);
        inited = 1;
    }

    // main stream: copy; fork panels onto sT
    copy_kernel<<<(BATCH * NN / 4 + 255) / 256, 256>>>(x);
    cudaEventRecord(evC, 0);
    cudaStreamWaitEvent(sT, evC, 0);
    lu_panel<<<BATCH, 512, 0, sT>>>(0);
    cudaEventRecord(evF[0], sT);
    lu_panel<<<BATCH, 512, 0, sT>>>(1);   // narrow cols of panel 1 are original data
    cudaEventRecord(evF[1], sT);

    for (int k = 0; k < 30; k++) {
        cudaStreamWaitEvent(0, evF[k], 0);       // wide(k) needs panel(k)'s L21/D/perm
        int coff = k * NB + 2 * NB;
        int Wc = N - coff;
        int Wr = N - (k * NB + NB);
        dim3 g((Wc + 63) / 64, (Wr + 127) / 128, BATCH);
        lu_wide<<<g, 256>>>(k);
        cudaEventRecord(evW[k], 0);
        // panel(k+2)'s narrow cols were last written by wide(k)
        cudaStreamWaitEvent(sT, evW[k], 0);
        lu_panel<<<BATCH, 512, 0, sT>>>(k + 2);
        cudaEventRecord(evF[k + 2], sT);
    }

    // join: everything after needs all panels (logdets)
    cudaStreamWaitEvent(0, evF[31], 0);
    head_kernel<<<1, 1>>>(flags, w1, b1, w2, b2, out, out_size);
    combine_kernel<<<(NN / 4 + 255) / 256, 256>>>(x);
    final_kernel<<<dim3(16, 8), 256, fin_smem>>>(x, out, out_size);
}

// round 5
// speedup vs baseline: 1.3338x; 1.3338x over previous
#include <cuda_runtime.h>
#include <math.h>

#define N     1024
#define NN    (N*N)
#define NB    32
#define NSTEP 32
#define BATCH 16

// ---------------- device scratch (no allocations allowed) ----------------
__device__ float g_lu[(size_t)BATCH * NN];   // 64 MB destructible LU workspace
__device__ float g_comb[(size_t)3 * NN];     // combined right-hand matrices C0,C1,C2
__device__ float g_logdet[BATCH];

struct Hdr {
    int   active;
    int   idx[8];
    float weff[10];
    float beff;
};
__device__ Hdr g_hdr;

// ---------------- stage A: copy x -> LU workspace, zero logdets ----------------
__global__ void copy_kernel(const float* __restrict__ x) {
    size_t i = (size_t)blockIdx.x * blockDim.x + threadIdx.x;
    const float4* src = (const float4*)x;
    float4* dst = (float4*)g_lu;
    if (i < (size_t)BATCH * NN / 4) dst[i] = src[i];
    if (i < BATCH) g_logdet[i] = 0.0f;
}

// ---------------- stage B1: panel factorization, register shift-array scheme ----
// One CTA per matrix, 512 threads, 2 register rows per thread. Row storage is a
// 32-wide shift array: current pivot column is ALWAYS position 0; elimination
// writes shifted (c[t-1] = c[t] - lv*piv[t]) and deposits lv at position 31.
// After 32 steps an L21 row's 32 L values sit at static positions 0..31.
// Pivot policy identical to R3: max |col value|, smaller index wins ties.
// After factoring, the CTA applies the 32 row swaps to trailing columns.
__global__ void __launch_bounds__(512) lu_panel(int k) {
    int m = blockIdx.x;
    float* A = g_lu + (size_t)m * NN;
    int kb = k * NB;
    int R  = N - kb;
    int W  = N - kb - NB;
    int tid = threadIdx.x;

    __shared__ float s_piv[NB];     // staged pivot row, zero-padded past active width
    __shared__ float s_rowj[NB];    // old logical row j content (for exchange)
    __shared__ float rv[16];
    __shared__ int   ri[16];
    __shared__ int   s_list[NB];    // pivot relative indices (for trailing swaps)

    int relA = tid, relB = tid + 512;
    bool hasA = relA < R, hasB = relB < R;

    float ca[NB], cb[NB];
    {
        const float4* pa = (const float4*)(A + (size_t)(kb + relA) * N + kb);
        const float4* pb = (const float4*)(A + (size_t)(kb + relB) * N + kb);
        #pragma unroll
        for (int q = 0; q < 8; q++) {
            float4 v = hasA ? pa[q] : make_float4(0.f, 0.f, 0.f, 0.f);
            ca[4*q+0] = v.x; ca[4*q+1] = v.y; ca[4*q+2] = v.z; ca[4*q+3] = v.w;
            float4 w = hasB ? pb[q] : make_float4(0.f, 0.f, 0.f, 0.f);
            cb[4*q+0] = w.x; cb[4*q+1] = w.y; cb[4*q+2] = w.z; cb[4*q+3] = w.w;
        }
    }

    float sld = 0.0f;
    #pragma unroll 1
    for (int j = 0; j < NB; j++) {
        // ---- pivot search: current column value is at static position 0 ----
        float cand = -1.0f; int ci = 0x7fffffff;
        if (hasA && relA >= j) { cand = fabsf(ca[0]); ci = relA; }
        if (hasB && relB >= j) {
            float v = fabsf(cb[0]);
            if (v > cand) { cand = v; ci = relB; }   // relB > relA always: tie -> relA
        }
        float best = cand; int bi = ci;
        #pragma unroll
        for (int o = 16; o > 0; o >>= 1) {
            float ov = __shfl_down_sync(0xffffffffu, best, o);
            int   oi = __shfl_down_sync(0xffffffffu, bi, o);
            if (ov > best || (ov == best && oi < bi)) { best = ov; bi = oi; }
        }
        if ((tid & 31) == 0) { rv[tid >> 5] = best; ri[tid >> 5] = bi; }
        __syncthreads();
        if (tid < 32) {
            float b2 = (tid < 16) ? rv[tid] : -2.0f;
            int   i2 = (tid < 16) ? ri[tid] : 0x7fffffff;
            #pragma unroll
            for (int o = 8; o > 0; o >>= 1) {
                float ov = __shfl_down_sync(0xffffffffu, b2, o);
                int   oi = __shfl_down_sync(0xffffffffu, i2, o);
                if (ov > b2 || (ov == b2 && oi < i2)) { b2 = ov; i2 = oi; }
            }
            if (tid == 0) {
                s_list[j] = i2;
                sld += logf(fmaxf(b2, 1e-45f));
            }
        }
        __syncthreads();
        int p = s_list[j];

        // ---- pivot holder: write exited row j to global (de-rotated) + stage s_piv ----
        bool ownA = (relA == p), ownB = (hasB && relB == p);
        if (ownA || ownB) {
            float* arow = A + (size_t)(kb + j) * N + kb;
            #pragma unroll
            for (int t = 0; t < NB; t++) {
                float v = ownA ? ca[t] : cb[t];
                int col = (t <= NB - 1 - j) ? (j + t) : (t - (NB - j));
                arow[col] = v;
                s_piv[t] = (t <= NB - 1 - j) ? v : 0.0f;   // zero-pad deposit region
            }
        }
        if (p != j && relA == j) {
            #pragma unroll
            for (int t = 0; t < NB; t++) s_rowj[t] = ca[t];
        }
        __syncthreads();

        // ---- exchange: pivot holder adopts old row j content (logical pos p) ----
        if (p != j) {
            if (ownA) {
                #pragma unroll
                for (int t = 0; t < NB; t++) ca[t] = s_rowj[t];
            } else if (ownB) {
                #pragma unroll
                for (int t = 0; t < NB; t++) cb[t] = s_rowj[t];
            }
        }

        // ---- shifted elimination + L deposit ----
        float inv = 1.0f / s_piv[0];
        if (hasA && relA > j) {
            float lv = ca[0] * inv;
            #pragma unroll
            for (int t = 1; t < NB; t++) ca[t-1] = ca[t] - lv * s_piv[t];
            ca[NB-1] = lv;
        }
        if (hasB && relB > j) {
            float lv = cb[0] * inv;
            #pragma unroll
            for (int t = 1; t < NB; t++) cb[t-1] = cb[t] - lv * s_piv[t];
            cb[NB-1] = lv;
        }
    }
    __syncthreads();

    // ---- L21 writeback: rows rel >= NB hold 32 L values at positions 0..31 ----
    if (hasA && relA >= NB) {
        float4* pw = (float4*)(A + (size_t)(kb + relA) * N + kb);
        #pragma unroll
        for (int q = 0; q < 8; q++)
            pw[q] = make_float4(ca[4*q+0], ca[4*q+1], ca[4*q+2], ca[4*q+3]);
    }
    if (hasB) {                                    // relB >= 512 >= NB always
        float4* pw = (float4*)(A + (size_t)(kb + relB) * N + kb);
        #pragma unroll
        for (int q = 0; q < 8; q++)
            pw[q] = make_float4(cb[4*q+0], cb[4*q+1], cb[4*q+2], cb[4*q+3]);
    }
    if (tid == 0) g_logdet[m] += sld;

    // ---- apply row swaps to trailing columns (column-local, coalesced) ----
    for (int c = tid; c < W; c += 512) {
        int col = kb + NB + c;
        #pragma unroll 1
        for (int j = 0; j < NB; j++) {
            int p = s_list[j];
            if (p != j) {
                float t1 = A[(size_t)(kb + j) * N + col];
                A[(size_t)(kb + j) * N + col] = A[(size_t)(kb + p) * N + col];
                A[(size_t)(kb + p) * N + col] = t1;
            }
        }
    }
}

// ---------------- stage B2: fused local-TRSM + trailing update (128x128, 8x8) ----
__global__ void __launch_bounds__(256) lu_update(int k) {
    int kb  = k * NB;
    int off = kb + NB;
    int W   = N - off;
    int m   = blockIdx.z;
    float* A = g_lu + (size_t)m * NN;
    int r0 = blockIdx.y * 128, c0 = blockIdx.x * 128;
    int tid = threadIdx.x;

    __shared__ float D[NB][NB + 1];     // factored diag block (L unit-lower + U)
    __shared__ float sL[128][NB + 1];   // L21 strip (this CTA's rows)
    __shared__ float sU[NB][132];       // U12 strip (this CTA's 128 cols)

    for (int i = tid; i < NB * NB; i += 256) {
        int r = i / NB, c = i % NB;
        D[r][c] = A[(size_t)(kb + r) * N + kb + c];
    }
    for (int i = tid; i < 128 * NB; i += 256) {
        int r = i / NB, j = i % NB;
        sL[r][j] = (r0 + r < W) ? A[(size_t)(off + r0 + r) * N + kb + j] : 0.0f;
    }
    for (int i = tid; i < NB * 128; i += 256) {
        int r = i / 128, c = i % 128;
        int col = c0 + c;
        sU[r][c] = (col < W) ? A[(size_t)(kb + r) * N + off + col] : 0.0f;
    }
    __syncthreads();

    // local TRSM: threads 0..127 each solve one U12 column (L11 unit-lower)
    if (tid < 128) {
        float v[NB];
        #pragma unroll
        for (int i = 0; i < NB; i++) v[i] = sU[i][tid];
        #pragma unroll 1
        for (int j = 0; j < NB; j++) {
            float vj = v[j];
            #pragma unroll
            for (int i = 0; i < NB; i++)
                if (i > j) v[i] -= D[i][j] * vj;
        }
        #pragma unroll
        for (int i = 0; i < NB; i++) sU[i][tid] = v[i];
    }
    __syncthreads();

    // trailing update: 128x128 tile, 8x8 per thread (two 64-col halves)
    int tx = tid & 15, ty = tid >> 4;
    float acc[8][8] = {};
    #pragma unroll
    for (int j = 0; j < NB; j++) {
        float4 b0 = *(const float4*)&sU[j][tx * 4];
        float4 b1 = *(const float4*)&sU[j][64 + tx * 4];
        float b[8] = {b0.x, b0.y, b0.z, b0.w, b1.x, b1.y, b1.z, b1.w};
        float a[8];
        #pragma unroll
        for (int i = 0; i < 8; i++) a[i] = sL[ty * 8 + i][j];
        #pragma unroll
        for (int i = 0; i < 8; i++)
            #pragma unroll
            for (int l = 0; l < 8; l++) acc[i][l] += a[i] * b[l];
    }
    #pragma unroll
    for (int i = 0; i < 8; i++) {
        int row = r0 + ty * 8 + i;
        if (row >= W) continue;
        float* orow = A + (size_t)(off + row) * N + off;
        #pragma unroll
        for (int l = 0; l < 8; l++) {
            int col = c0 + ((l < 4) ? (tx * 4 + l) : (64 + tx * 4 + l - 4));
            if (col < W) orow[col] -= acc[i][l];
        }
    }
}

// ---------------- stage C: scores, top-k, fused weights, bool output ----------------
__global__ void head_kernel(const unsigned char* __restrict__ flags,
                            const float* __restrict__ w1, const float* __restrict__ b1,
                            const float* __restrict__ w2, const float* __restrict__ b2,
                            float* __restrict__ out, int out_size) {
    if (blockIdx.x != 0 || threadIdx.x != 0) return;

    int f[16];
    bool any_off4 = false;
    for (int i = 0; i < 16; i++)
        if ((i & 3) && flags[i]) any_off4 = true;
    if (any_off4) {
        for (int i = 0; i < 16; i++) f[i] = flags[i] ? 1 : 0;
    } else {
        const int* fi = (const int*)flags;
        for (int i = 0; i < 16; i++) f[i] = fi[i] ? 1 : 0;
    }

    int sum = 0;
    for (int i = 0; i < 16; i++) sum += f[i];
    int active = (sum >= 4) ? 1 : 0;

    float neg_inf = __int_as_float(0xff800000);
    float sc[16];
    for (int i = 0; i < 16; i++) sc[i] = f[i] ? g_logdet[i] : neg_inf;

    int used[16] = {};
    for (int t = 0; t < 8; t++) {
        int best = -1;
        float bv = neg_inf;
        for (int i = 0; i < 16; i++) {
            if (used[i]) continue;
            if (best < 0 || sc[i] > bv) { best = i; bv = sc[i]; }
        }
        used[best] = 1;
        g_hdr.idx[t] = best;
    }

    for (int c = 0; c < 10; c++) {
        float a = 0.0f;
        for (int h = 0; h < 32; h++) a += w2[h] * w1[h * 10 + c];
        g_hdr.weff[c] = a;
    }
    float be = b2[0];
    for (int h = 0; h < 32; h++) be += w2[h] * b1[h];
    g_hdr.beff = be;
    g_hdr.active = active;

    for (int i = NN; i < out_size; i++) out[i] = active ? 1.0f : 0.0f;
}

// ---------------- stage D1: combined right matrices ----------------
__global__ void combine_kernel(const float* __restrict__ x) {
    int i = blockIdx.x * blockDim.x + threadIdx.x;
    if (i >= NN / 4) return;
    const float4* T1 = (const float4*)(x + (size_t)g_hdr.idx[1] * NN);
    const float4* T2 = (const float4*)(x + (size_t)g_hdr.idx[2] * NN);
    const float4* T3 = (const float4*)(x + (size_t)g_hdr.idx[3] * NN);
    float w0 = g_hdr.weff[0], w1 = g_hdr.weff[1], w2 = g_hdr.weff[2];
    float w3 = g_hdr.weff[3], w4 = g_hdr.weff[4], w5 = g_hdr.weff[5];
    float4 a = T1[i], b = T2[i], c = T3[i];
    float4 r0, r1, r2;
    r0.x = w0*a.x + w1*b.x + w2*c.x;  r0.y = w0*a.y + w1*b.y + w2*c.y;
    r0.z = w0*a.z + w1*b.z + w2*c.z;  r0.w = w0*a.w + w1*b.w + w2*c.w;
    r1.x = w3*b.x + w4*c.x;  r1.y = w3*b.y + w4*c.y;
    r1.z = w3*b.z + w4*c.z;  r1.w = w3*b.w + w4*c.w;
    r2.x = w5*c.x;  r2.y = w5*c.y;  r2.z = w5*c.z;  r2.w = w5*c.w;
    ((float4*)g_comb)[i]            = r0;
    ((float4*)(g_comb + NN))[i]     = r1;
    ((float4*)(g_comb + 2*NN))[i]   = r2;
}

// ---------------- stage D2: fused 3-GEMM + preserve channels + bias ----------------
#define SA(p,r,j) sA[((p) * 128 + (r)) * 33 + (j)]
#define SB(p,j,c) sB[((p) * NB + (j)) * 68 + (c)]
__global__ void __launch_bounds__(256) final_kernel(const float* __restrict__ x,
                                                    float* __restrict__ out, int out_size) {
    extern __shared__ float sm[];
    float* sA = sm;                         // 3 * 128 * 33
    float* sB = sm + 3 * 128 * 33;          // 3 * NB * 68

    int r0 = blockIdx.y * 128, c0 = blockIdx.x * 64;
    int tid = threadIdx.x, tx = tid & 15, ty = tid >> 4;

    if (!g_hdr.active) {
        #pragma unroll
        for (int i = 0; i < 8; i++) {
            int row = r0 + ty * 8 + i;
            #pragma unroll
            for (int l = 0; l < 4; l++) {
                int p = row * N + c0 + tx * 4 + l;
                if (p < out_size) out[p] = 0.0f;
            }
        }
        return;
    }

    const float* L[3] = { x + (size_t)g_hdr.idx[0] * NN,
                          x + (size_t)g_hdr.idx[1] * NN,
                          x + (size_t)g_hdr.idx[2] * NN };
    const float* C[3] = { g_comb, g_comb + NN, g_comb + 2 * NN };

    float acc[8][4] = {};
    for (int kc = 0; kc < N; kc += NB) {
        #pragma unroll
        for (int p = 0; p < 3; p++) {
            for (int i = tid; i < 128 * NB; i += 256) {
                int r = i / NB, j = i % NB;
                SA(p, r, j) = L[p][(size_t)(r0 + r) * N + kc + j];
            }
            for (int i = tid; i < NB * 64; i += 256) {
                int j = i / 64, c = i % 64;
                SB(p, j, c) = C[p][(size_t)(kc + j) * N + c0 + c];
            }
        }
        __syncthreads();
        #pragma unroll 4
        for (int jj = 0; jj < NB; jj++) {
            #pragma unroll
            for (int p = 0; p < 3; p++) {
                float4 bv = *(const float4*)&SB(p, jj, tx * 4);
                float b[4] = {bv.x, bv.y, bv.z, bv.w};
                float a[8];
                #pragma unroll
                for (int i = 0; i < 8; i++) a[i] = SA(p, ty * 8 + i, jj);
                #pragma unroll
                for (int i = 0; i < 8; i++)
                    #pragma unroll
                    for (int l = 0; l < 4; l++) acc[i][l] += a[i] * b[l];
            }
        }
        __syncthreads();
    }

    const float* P0 = x + (size_t)g_hdr.idx[4] * NN;
    const float* P1 = x + (size_t)g_hdr.idx[5] * NN;
    const float* P2 = x + (size_t)g_hdr.idx[6] * NN;
    const float* P3 = x + (size_t)g_hdr.idx[7] * NN;
    float w6 = g_hdr.weff[6], w7 = g_hdr.weff[7], w8 = g_hdr.weff[8], w9 = g_hdr.weff[9];
    float be = g_hdr.beff;

    #pragma unroll
    for (int i = 0; i < 8; i++) {
        int row = r0 + ty * 8 + i;
        #pragma unroll
        for (int l = 0; l < 4; l++) {
            int col = c0 + tx * 4 + l;
            int p = row * N + col;
            float v = acc[i][l] + w6 * P0[p] + w7 * P1[p] + w8 * P2[p] + w9 * P3[p] + be;
            if (p < out_size) out[p] = v;
        }
    }
}

// ---------------- host launcher ----------------
extern "C" void kernel_launch(void* const* d_in, const int* in_sizes, int n_in,
                              void* d_out, int out_size) {
    const float*         x     = (const float*)d_in[0];
    const unsigned char* flags = (const unsigned char*)d_in[1];
    const float*         w1    = (const float*)d_in[2];
    const float*         b1    = (const float*)d_in[3];
    const float*         w2    = (const float*)d_in[4];
    const float*         b2    = (const float*)d_in[5];
    float*               out   = (float*)d_out;

    int fin_smem = (3 * 128 * 33 + 3 * NB * 68) * (int)sizeof(float);
    cudaFuncSetAttribute(final_kernel, cudaFuncAttributeMaxDynamicSharedMemorySize, fin_smem);

    copy_kernel<<<(BATCH * NN / 4 + 255) / 256, 256>>>(x);

    for (int k = 0; k < NSTEP; k++) {
        int W = N - (k + 1) * NB;
        lu_panel<<<BATCH, 512>>>(k);
        if (W > 0) {
            dim3 g((W + 127) / 128, (W + 127) / 128, BATCH);
            lu_update<<<g, 256>>>(k);
        }
    }

    head_kernel<<<1, 1>>>(flags, w1, b1, w2, b2, out, out_size);
    combine_kernel<<<(NN / 4 + 255) / 256, 256>>>(x);
    final_kernel<<<dim3(16, 8), 256, fin_smem>>>(x, out, out_size);
}

// round 6
// speedup vs baseline: 1.5156x; 1.1364x over previous
#include <cuda_runtime.h>
#include <math.h>

#define N     1024
#define NN    (N*N)
#define NB    32
#define NSTEP 32
#define BATCH 16

// ---------------- device scratch (no allocations allowed) ----------------
__device__ float g_lu[(size_t)BATCH * NN];     // 64 MB destructible LU workspace
__device__ float g_comb[(size_t)3 * NN];       // combined right-hand matrices C0,C1,C2
__device__ float g_logdet[BATCH];
__device__ float g_swaptmp[(size_t)BATCH * 64 * N];  // row-gather staging (4 MB)

struct Hdr {
    int   active;
    int   idx[8];
    float weff[10];
    float beff;
};
__device__ Hdr g_hdr;

// ---------------- stage A: copy x -> LU workspace, zero logdets ----------------
__global__ void copy_kernel(const float* __restrict__ x) {
    size_t i = (size_t)blockIdx.x * blockDim.x + threadIdx.x;
    const float4* src = (const float4*)x;
    float4* dst = (float4*)g_lu;
    if (i < (size_t)BATCH * NN / 4) dst[i] = src[i];
    if (i < BATCH) g_logdet[i] = 0.0f;
}

// ---------------- stage B1: panel factorization, relabeling shift-array scheme ----
// One CTA per matrix, 512 threads, 2 register rows/thread. Register rows never
// move; a logical-position tag (myrel) tracks pivot swaps. Pivot owner exits its
// row into the shared U block. Per step: one 64-bit-key warp reduce, redundant
// 16-way scan (no 2nd reduce level), 2 syncs. Shift-array elimination: pivot
// column is always register slot 0; L multiplier deposited at slot 31.
// Trailing-column swaps become a permutation gather (<=64 rows) via global tmp.
__global__ void __launch_bounds__(512) lu_panel(int k) {
    int m = blockIdx.x;
    float* A = g_lu + (size_t)m * NN;
    float* tmp = g_swaptmp + (size_t)m * 64 * N;
    int kb = k * NB;
    int R  = N - kb;
    int W  = N - kb - NB;
    int tid = threadIdx.x;
    int lane = tid & 31, wrp = tid >> 5;

    __shared__ unsigned long long rvi[16];
    __shared__ float s_piv[NB];          // staged pivot row (shift layout, zero-padded)
    __shared__ float s_U[NB][NB + 1];    // de-rotated exited rows (L|U of diag block)
    __shared__ float s_abs[NB];          // |pivot| per step (logs computed at end)
    __shared__ int   s_src[N];           // final logical slot -> original rel
    __shared__ int   s_aff[64];
    __shared__ int   s_na;

    int relA = tid, relB = tid + 512;
    bool actA = relA < R, actB = relB < R;
    int myA = relA, myB = relB;          // logical positions
    int exA = -1, exB = -1;              // exit step if row became pivot

    float ca[NB], cb[NB];
    {
        const float4* pa = (const float4*)(A + (size_t)(kb + relA) * N + kb);
        const float4* pb = (const float4*)(A + (size_t)(kb + relB) * N + kb);
        #pragma unroll
        for (int q = 0; q < 8; q++) {
            float4 v = actA ? pa[q] : make_float4(0.f, 0.f, 0.f, 0.f);
            ca[4*q+0] = v.x; ca[4*q+1] = v.y; ca[4*q+2] = v.z; ca[4*q+3] = v.w;
            float4 w = actB ? pb[q] : make_float4(0.f, 0.f, 0.f, 0.f);
            cb[4*q+0] = w.x; cb[4*q+1] = w.y; cb[4*q+2] = w.z; cb[4*q+3] = w.w;
        }
    }
    if (tid == 0) s_na = 0;

    #pragma unroll 1
    for (int j = 0; j < NB; j++) {
        // ---- candidate key: (|value| bits << 32) | (~logical index) ----
        unsigned long long key = 0ull;
        if (actA)
            key = ((unsigned long long)__float_as_uint(fabsf(ca[0])) << 32)
                | (unsigned long long)(0xFFFFFFFFu - (unsigned)myA);
        if (actB) {
            unsigned long long k2 =
                  ((unsigned long long)__float_as_uint(fabsf(cb[0])) << 32)
                | (unsigned long long)(0xFFFFFFFFu - (unsigned)myB);
            if (k2 > key) key = k2;
        }
        #pragma unroll
        for (int o = 16; o > 0; o >>= 1) {
            unsigned long long ok = __shfl_down_sync(0xffffffffu, key, o);
            if (ok > key) key = ok;
        }
        if (lane == 0) rvi[wrp] = key;
        __syncthreads();

        // ---- redundant 16-way scan: every thread learns the pivot ----
        unsigned long long bk = rvi[0];
        #pragma unroll
        for (int w = 1; w < 16; w++) if (rvi[w] > bk) bk = rvi[w];
        int p = (int)(0xFFFFFFFFu - (unsigned)(bk & 0xFFFFFFFFull));
        if (tid == 0) s_abs[j] = __uint_as_float((unsigned)(bk >> 32));

        // ---- owner exits; logical slot j relabels to p (no content motion) ----
        if (actA) {
            if (myA == p) {
                #pragma unroll
                for (int t = 0; t < NB; t++) {
                    float v = ca[t];
                    int col = (t <= NB - 1 - j) ? (j + t) : (t - (NB - j));
                    s_U[j][col] = v;
                    s_piv[t] = (t <= NB - 1 - j) ? v : 0.0f;
                }
                actA = false; exA = j;
            } else if (myA == j) myA = p;
        }
        if (actB) {
            if (myB == p) {
                #pragma unroll
                for (int t = 0; t < NB; t++) {
                    float v = cb[t];
                    int col = (t <= NB - 1 - j) ? (j + t) : (t - (NB - j));
                    s_U[j][col] = v;
                    s_piv[t] = (t <= NB - 1 - j) ? v : 0.0f;
                }
                actB = false; exB = j;
            } else if (myB == j) myB = p;
        }
        __syncthreads();

        // ---- shifted elimination + L deposit ----
        float inv = 1.0f / s_piv[0];
        if (actA) {
            float lv = ca[0] * inv;
            #pragma unroll
            for (int t = 1; t < NB; t++) ca[t-1] = ca[t] - lv * s_piv[t];
            ca[NB-1] = lv;
        }
        if (actB) {
            float lv = cb[0] * inv;
            #pragma unroll
            for (int t = 1; t < NB; t++) cb[t-1] = cb[t] - lv * s_piv[t];
            cb[NB-1] = lv;
        }
    }
    __syncthreads();

    // ---- diag block writeback (L|U of the 32 exited rows) ----
    for (int i = tid; i < NB * NB; i += 512)
        A[(size_t)(kb + i / NB) * N + kb + (i % NB)] = s_U[i / NB][i % NB];

    // ---- L21 writeback: surviving rows land at their final logical slot ----
    if (actA) {
        float4* pw = (float4*)(A + (size_t)(kb + myA) * N + kb);
        #pragma unroll
        for (int q = 0; q < 8; q++)
            pw[q] = make_float4(ca[4*q+0], ca[4*q+1], ca[4*q+2], ca[4*q+3]);
    }
    if (actB) {
        float4* pw = (float4*)(A + (size_t)(kb + myB) * N + kb);
        #pragma unroll
        for (int q = 0; q < 8; q++)
            pw[q] = make_float4(cb[4*q+0], cb[4*q+1], cb[4*q+2], cb[4*q+3]);
    }

    // ---- logdet: 32 parallel logs + warp-reduce sum ----
    if (tid < 32) {
        float lg = logf(fmaxf(s_abs[tid], 1e-45f));
        #pragma unroll
        for (int o = 16; o > 0; o >>= 1) lg += __shfl_down_sync(0xffffffffu, lg, o);
        if (tid == 0) g_logdet[m] += lg;
    }

    // ---- build source map: final content of slot r = original row src[r] ----
    if (relA < R) {
        if (exA >= 0) s_src[exA] = relA; else s_src[myA] = relA;
    }
    if (relB < R) {
        if (exB >= 0) s_src[exB] = relB; else s_src[myB] = relB;
    }
    __syncthreads();
    for (int r = tid; r < R; r += 512) {
        if (s_src[r] != r) {
            int i = atomicAdd(&s_na, 1);
            s_aff[i] = r;
        }
    }
    __syncthreads();
    int na = s_na;
    if (W <= 0 || na == 0) return;

    // ---- permutation gather on trailing columns: two coalesced passes ----
    int W4 = W >> 2;
    for (int idx = tid; idx < na * W4; idx += 512) {
        int i = idx / W4, c = idx % W4;
        int sr = s_src[s_aff[i]];
        *(float4*)(tmp + (size_t)i * W + 4 * c) =
            *(const float4*)(A + (size_t)(kb + sr) * N + kb + NB + 4 * c);
    }
    __syncthreads();
    for (int idx = tid; idx < na * W4; idx += 512) {
        int i = idx / W4, c = idx % W4;
        int dr = s_aff[i];
        *(float4*)(A + (size_t)(kb + dr) * N + kb + NB + 4 * c) =
            *(const float4*)(tmp + (size_t)i * W + 4 * c);
    }
}

// ---------------- stage B2: fused local-TRSM + trailing update (128x128, 8x8) ----
__global__ void __launch_bounds__(256) lu_update(int k) {
    int kb  = k * NB;
    int off = kb + NB;
    int W   = N - off;
    int m   = blockIdx.z;
    float* A = g_lu + (size_t)m * NN;
    int r0 = blockIdx.y * 128, c0 = blockIdx.x * 128;
    int tid = threadIdx.x;

    __shared__ float D[NB][NB + 1];     // factored diag block (L unit-lower + U)
    __shared__ float sL[128][NB + 1];   // L21 strip (this CTA's rows)
    __shared__ float sU[NB][132];       // U12 strip (this CTA's 128 cols)

    for (int i = tid; i < NB * NB; i += 256) {
        int r = i / NB, c = i % NB;
        D[r][c] = A[(size_t)(kb + r) * N + kb + c];
    }
    for (int i = tid; i < 128 * NB; i += 256) {
        int r = i / NB, j = i % NB;
        sL[r][j] = (r0 + r < W) ? A[(size_t)(off + r0 + r) * N + kb + j] : 0.0f;
    }
    for (int i = tid; i < NB * 128; i += 256) {
        int r = i / 128, c = i % 128;
        int col = c0 + c;
        sU[r][c] = (col < W) ? A[(size_t)(kb + r) * N + off + col] : 0.0f;
    }
    __syncthreads();

    // local TRSM: threads 0..127 each solve one U12 column (L11 unit-lower)
    if (tid < 128) {
        float v[NB];
        #pragma unroll
        for (int i = 0; i < NB; i++) v[i] = sU[i][tid];
        #pragma unroll 1
        for (int j = 0; j < NB; j++) {
            float vj = v[j];
            #pragma unroll
            for (int i = 0; i < NB; i++)
                if (i > j) v[i] -= D[i][j] * vj;
        }
        #pragma unroll
        for (int i = 0; i < NB; i++) sU[i][tid] = v[i];
    }
    __syncthreads();

    // trailing update: 128x128 tile, 8x8 per thread (two 64-col halves)
    int tx = tid & 15, ty = tid >> 4;
    float acc[8][8] = {};
    #pragma unroll
    for (int j = 0; j < NB; j++) {
        float4 b0 = *(const float4*)&sU[j][tx * 4];
        float4 b1 = *(const float4*)&sU[j][64 + tx * 4];
        float b[8] = {b0.x, b0.y, b0.z, b0.w, b1.x, b1.y, b1.z, b1.w};
        float a[8];
        #pragma unroll
        for (int i = 0; i < 8; i++) a[i] = sL[ty * 8 + i][j];
        #pragma unroll
        for (int i = 0; i < 8; i++)
            #pragma unroll
            for (int l = 0; l < 8; l++) acc[i][l] += a[i] * b[l];
    }
    #pragma unroll
    for (int i = 0; i < 8; i++) {
        int row = r0 + ty * 8 + i;
        if (row >= W) continue;
        float* orow = A + (size_t)(off + row) * N + off;
        #pragma unroll
        for (int l = 0; l < 8; l++) {
            int col = c0 + ((l < 4) ? (tx * 4 + l) : (64 + tx * 4 + l - 4));
            if (col < W) orow[col] -= acc[i][l];
        }
    }
}

// ---------------- stage C: scores, top-k, fused weights, bool output ----------------
__global__ void head_kernel(const unsigned char* __restrict__ flags,
                            const float* __restrict__ w1, const float* __restrict__ b1,
                            const float* __restrict__ w2, const float* __restrict__ b2,
                            float* __restrict__ out, int out_size) {
    if (blockIdx.x != 0 || threadIdx.x != 0) return;

    int f[16];
    bool any_off4 = false;
    for (int i = 0; i < 16; i++)
        if ((i & 3) && flags[i]) any_off4 = true;
    if (any_off4) {
        for (int i = 0; i < 16; i++) f[i] = flags[i] ? 1 : 0;
    } else {
        const int* fi = (const int*)flags;
        for (int i = 0; i < 16; i++) f[i] = fi[i] ? 1 : 0;
    }

    int sum = 0;
    for (int i = 0; i < 16; i++) sum += f[i];
    int active = (sum >= 4) ? 1 : 0;

    float neg_inf = __int_as_float(0xff800000);
    float sc[16];
    for (int i = 0; i < 16; i++) sc[i] = f[i] ? g_logdet[i] : neg_inf;

    int used[16] = {};
    for (int t = 0; t < 8; t++) {
        int best = -1;
        float bv = neg_inf;
        for (int i = 0; i < 16; i++) {
            if (used[i]) continue;
            if (best < 0 || sc[i] > bv) { best = i; bv = sc[i]; }
        }
        used[best] = 1;
        g_hdr.idx[t] = best;
    }

    for (int c = 0; c < 10; c++) {
        float a = 0.0f;
        for (int h = 0; h < 32; h++) a += w2[h] * w1[h * 10 + c];
        g_hdr.weff[c] = a;
    }
    float be = b2[0];
    for (int h = 0; h < 32; h++) be += w2[h] * b1[h];
    g_hdr.beff = be;
    g_hdr.active = active;

    for (int i = NN; i < out_size; i++) out[i] = active ? 1.0f : 0.0f;
}

// ---------------- stage D1: combined right matrices ----------------
__global__ void combine_kernel(const float* __restrict__ x) {
    int i = blockIdx.x * blockDim.x + threadIdx.x;
    if (i >= NN / 4) return;
    const float4* T1 = (const float4*)(x + (size_t)g_hdr.idx[1] * NN);
    const float4* T2 = (const float4*)(x + (size_t)g_hdr.idx[2] * NN);
    const float4* T3 = (const float4*)(x + (size_t)g_hdr.idx[3] * NN);
    float w0 = g_hdr.weff[0], w1 = g_hdr.weff[1], w2 = g_hdr.weff[2];
    float w3 = g_hdr.weff[3], w4 = g_hdr.weff[4], w5 = g_hdr.weff[5];
    float4 a = T1[i], b = T2[i], c = T3[i];
    float4 r0, r1, r2;
    r0.x = w0*a.x + w1*b.x + w2*c.x;  r0.y = w0*a.y + w1*b.y + w2*c.y;
    r0.z = w0*a.z + w1*b.z + w2*c.z;  r0.w = w0*a.w + w1*b.w + w2*c.w;
    r1.x = w3*b.x + w4*c.x;  r1.y = w3*b.y + w4*c.y;
    r1.z = w3*b.z + w4*c.z;  r1.w = w3*b.w + w4*c.w;
    r2.x = w5*c.x;  r2.y = w5*c.y;  r2.z = w5*c.z;  r2.w = w5*c.w;
    ((float4*)g_comb)[i]            = r0;
    ((float4*)(g_comb + NN))[i]     = r1;
    ((float4*)(g_comb + 2*NN))[i]   = r2;
}

// ---------------- stage D2: fused 3-GEMM + preserve channels + bias ----------------
#define SA(p,r,j) sA[((p) * 128 + (r)) * 33 + (j)]
#define SB(p,j,c) sB[((p) * NB + (j)) * 68 + (c)]
__global__ void __launch_bounds__(256) final_kernel(const float* __restrict__ x,
                                                    float* __restrict__ out, int out_size) {
    extern __shared__ float sm[];
    float* sA = sm;                         // 3 * 128 * 33
    float* sB = sm + 3 * 128 * 33;          // 3 * NB * 68

    int r0 = blockIdx.y * 128, c0 = blockIdx.x * 64;
    int tid = threadIdx.x, tx = tid & 15, ty = tid >> 4;

    if (!g_hdr.active) {
        #pragma unroll
        for (int i = 0; i < 8; i++) {
            int row = r0 + ty * 8 + i;
            #pragma unroll
            for (int l = 0; l < 4; l++) {
                int p = row * N + c0 + tx * 4 + l;
                if (p < out_size) out[p] = 0.0f;
            }
        }
        return;
    }

    const float* L[3] = { x + (size_t)g_hdr.idx[0] * NN,
                          x + (size_t)g_hdr.idx[1] * NN,
                          x + (size_t)g_hdr.idx[2] * NN };
    const float* C[3] = { g_comb, g_comb + NN, g_comb + 2 * NN };

    float acc[8][4] = {};
    for (int kc = 0; kc < N; kc += NB) {
        #pragma unroll
        for (int p = 0; p < 3; p++) {
            for (int i = tid; i < 128 * NB; i += 256) {
                int r = i / NB, j = i % NB;
                SA(p, r, j) = L[p][(size_t)(r0 + r) * N + kc + j];
            }
            for (int i = tid; i < NB * 64; i += 256) {
                int j = i / 64, c = i % 64;
                SB(p, j, c) = C[p][(size_t)(kc + j) * N + c0 + c];
            }
        }
        __syncthreads();
        #pragma unroll 4
        for (int jj = 0; jj < NB; jj++) {
            #pragma unroll
            for (int p = 0; p < 3; p++) {
                float4 bv = *(const float4*)&SB(p, jj, tx * 4);
                float b[4] = {bv.x, bv.y, bv.z, bv.w};
                float a[8];
                #pragma unroll
                for (int i = 0; i < 8; i++) a[i] = SA(p, ty * 8 + i, jj);
                #pragma unroll
                for (int i = 0; i < 8; i++)
                    #pragma unroll
                    for (int l = 0; l < 4; l++) acc[i][l] += a[i] * b[l];
            }
        }
        __syncthreads();
    }

    const float* P0 = x + (size_t)g_hdr.idx[4] * NN;
    const float* P1 = x + (size_t)g_hdr.idx[5] * NN;
    const float* P2 = x + (size_t)g_hdr.idx[6] * NN;
    const float* P3 = x + (size_t)g_hdr.idx[7] * NN;
    float w6 = g_hdr.weff[6], w7 = g_hdr.weff[7], w8 = g_hdr.weff[8], w9 = g_hdr.weff[9];
    float be = g_hdr.beff;

    #pragma unroll
    for (int i = 0; i < 8; i++) {
        int row = r0 + ty * 8 + i;
        #pragma unroll
        for (int l = 0; l < 4; l++) {
            int col = c0 + tx * 4 + l;
            int p = row * N + col;
            float v = acc[i][l] + w6 * P0[p] + w7 * P1[p] + w8 * P2[p] + w9 * P3[p] + be;
            if (p < out_size) out[p] = v;
        }
    }
}

// ---------------- host launcher ----------------
extern "C" void kernel_launch(void* const* d_in, const int* in_sizes, int n_in,
                              void* d_out, int out_size) {
    const float*         x     = (const float*)d_in[0];
    const unsigned char* flags = (const unsigned char*)d_in[1];
    const float*         w1    = (const float*)d_in[2];
    const float*         b1    = (const float*)d_in[3];
    const float*         w2    = (const float*)d_in[4];
    const float*         b2    = (const float*)d_in[5];
    float*               out   = (float*)d_out;

    int fin_smem = (3 * 128 * 33 + 3 * NB * 68) * (int)sizeof(float);
    cudaFuncSetAttribute(final_kernel, cudaFuncAttributeMaxDynamicSharedMemorySize, fin_smem);

    copy_kernel<<<(BATCH * NN / 4 + 255) / 256, 256>>>(x);

    for (int k = 0; k < NSTEP; k++) {
        int W = N - (k + 1) * NB;
        lu_panel<<<BATCH, 512>>>(k);
        if (W > 0) {
            dim3 g((W + 127) / 128, (W + 127) / 128, BATCH);
            lu_update<<<g, 256>>>(k);
        }
    }

    head_kernel<<<1, 1>>>(flags, w1, b1, w2, b2, out, out_size);
    combine_kernel<<<(NN / 4 + 255) / 256, 256>>>(x);
    final_kernel<<<dim3(16, 8), 256, fin_smem>>>(x, out, out_size);
}